// round 2
// baseline (speedup 1.0000x reference)
#include <cuda_runtime.h>

#define NC 384
#define NH 6
#define HD 64
#define NB 64
#define NT 256
#define NM (NB*NT)
#define SOFT_SCALE 0.125f

// scratch (allocation-free rule: __device__ globals)
__device__ float g_q[(size_t)NB*NH*NT*HD];
__device__ float g_k[(size_t)NB*NH*NT*HD];
__device__ float g_v[(size_t)NB*NH*NT*HD];
__device__ float g_att[(size_t)NB*NH*NT*HD];

// ---------------------------------------------------------------------------
// Kernel 1: QKV projection. grid (NM/64, 3*NH), block 256.
// q/k/v[b][h][t][d] = sum_c x[b][t][c] * W[h][c][d]
// ---------------------------------------------------------------------------
__global__ __launch_bounds__(256) void qkv_kernel(
    const float* __restrict__ x,
    const float* __restrict__ Wq,
    const float* __restrict__ Wk,
    const float* __restrict__ Wv)
{
    __shared__ float XsT[64][68];   // transposed: XsT[c][r]
    __shared__ float Ws[64][68];    // natural:    Ws[c][d]

    int mat = blockIdx.y / NH;
    int h   = blockIdx.y % NH;
    const float* W = (mat == 0 ? Wq : (mat == 1 ? Wk : Wv)) + (size_t)h * NC * HD;
    float* outp = (mat == 0 ? g_q : (mat == 1 ? g_k : g_v));

    int m0  = blockIdx.x * 64;
    int tid = threadIdx.x;
    int ty = tid >> 4, tx = tid & 15;

    float acc[4][4] = {};

    for (int c0 = 0; c0 < NC; c0 += 64) {
        __syncthreads();
        #pragma unroll
        for (int i = 0; i < 4; i++) {
            int e = tid + i * 256;
            int r = e >> 4, c4 = (e & 15) * 4;
            float4 v4 = *(const float4*)(x + (size_t)(m0 + r) * NC + c0 + c4);
            XsT[c4+0][r] = v4.x; XsT[c4+1][r] = v4.y;
            XsT[c4+2][r] = v4.z; XsT[c4+3][r] = v4.w;
        }
        #pragma unroll
        for (int i = 0; i < 4; i++) {
            int e = tid + i * 256;
            int c = e >> 4, d4 = (e & 15) * 4;
            *(float4*)&Ws[c][d4] = *(const float4*)(W + (size_t)(c0 + c) * HD + d4);
        }
        __syncthreads();

        #pragma unroll 16
        for (int kk = 0; kk < 64; kk++) {
            float4 a = *(float4*)&XsT[kk][ty*4];
            float4 b = *(float4*)&Ws[kk][tx*4];
            float av[4] = {a.x, a.y, a.z, a.w};
            float bv[4] = {b.x, b.y, b.z, b.w};
            #pragma unroll
            for (int i = 0; i < 4; i++)
                #pragma unroll
                for (int j = 0; j < 4; j++)
                    acc[i][j] += av[i] * bv[j];
        }
    }

    #pragma unroll
    for (int i = 0; i < 4; i++) {
        int m = m0 + ty*4 + i;
        int b = m / NT, t = m % NT;
        float4 v4 = make_float4(acc[i][0], acc[i][1], acc[i][2], acc[i][3]);
        *(float4*)(outp + ((size_t)(b*NH + h)*NT + t) * HD + tx*4) = v4;
    }
}

// ---------------------------------------------------------------------------
// Kernel 2: causal flash attention. grid (NT/64, NB*NH), block 256.
// Static smem (<=48KB): QsT, KP (K tile reused as transposed-P tile), Vs.
// Stride 64 floats: inner-loop reads are conflict-free (tx consecutive /
// ty broadcast); only the transposed stores pay conflicts.
// ---------------------------------------------------------------------------
__global__ __launch_bounds__(256) void attn_kernel()
{
    __shared__ float QsT[64][64];
    __shared__ float KP [64][64];   // KsT during S, then PsT during PV
    __shared__ float Vs [64][64];

    int qt = blockIdx.x;
    int bh = blockIdx.y;
    const float* qbase = g_q + (size_t)bh * NT * HD;
    const float* kbase = g_k + (size_t)bh * NT * HD;
    const float* vbase = g_v + (size_t)bh * NT * HD;

    int tid = threadIdx.x;
    int ty = tid >> 4, tx = tid & 15;

    // load Q tile transposed (QsT[d][r])
    #pragma unroll
    for (int i = 0; i < 4; i++) {
        int e = tid + i * 256;
        int r = e >> 4, c4 = (e & 15) * 4;
        float4 v4 = *(const float4*)(qbase + (size_t)(qt*64 + r) * HD + c4);
        QsT[c4+0][r] = v4.x; QsT[c4+1][r] = v4.y;
        QsT[c4+2][r] = v4.z; QsT[c4+3][r] = v4.w;
    }

    float o[4][4] = {};
    float mrow[4] = {-1e30f, -1e30f, -1e30f, -1e30f};
    float lrow[4] = {};

    for (int st = 0; st <= qt; st++) {
        __syncthreads();   // Q visibility (iter 0), KP/Vs reuse (later iters)
        #pragma unroll
        for (int i = 0; i < 4; i++) {
            int e = tid + i * 256;
            int r = e >> 4, c4 = (e & 15) * 4;
            float4 kv = *(const float4*)(kbase + (size_t)(st*64 + r) * HD + c4);
            KP[c4+0][r] = kv.x; KP[c4+1][r] = kv.y;
            KP[c4+2][r] = kv.z; KP[c4+3][r] = kv.w;
            float4 vv = *(const float4*)(vbase + (size_t)(st*64 + r) * HD + c4);
            *(float4*)&Vs[r][c4] = vv;
        }
        __syncthreads();

        // S = Q K^T for this tile
        float s[4][4] = {};
        #pragma unroll 16
        for (int kk = 0; kk < 64; kk++) {
            float4 a = *(float4*)&QsT[kk][ty*4];
            float4 b = *(float4*)&KP[kk][tx*4];
            float av[4] = {a.x, a.y, a.z, a.w};
            float bv[4] = {b.x, b.y, b.z, b.w};
            #pragma unroll
            for (int i = 0; i < 4; i++)
                #pragma unroll
                for (int j = 0; j < 4; j++)
                    s[i][j] += av[i] * bv[j];
        }

        // scale + causal mask (only diagonal tile needs masking)
        bool diag = (st == qt);
        #pragma unroll
        for (int i = 0; i < 4; i++) {
            int rg = qt*64 + ty*4 + i;
            #pragma unroll
            for (int j = 0; j < 4; j++) {
                int cg = st*64 + tx*4 + j;
                float val = s[i][j] * SOFT_SCALE;
                if (diag && cg > rg) val = -1e30f;
                s[i][j] = val;
            }
        }

        // online softmax; rows reduced across the 16 tx lanes (shfl only)
        #pragma unroll
        for (int i = 0; i < 4; i++) {
            float mx = fmaxf(fmaxf(s[i][0], s[i][1]), fmaxf(s[i][2], s[i][3]));
            #pragma unroll
            for (int off = 1; off < 16; off <<= 1)
                mx = fmaxf(mx, __shfl_xor_sync(0xffffffffu, mx, off));
            float mnew = fmaxf(mrow[i], mx);
            float corr = __expf(mrow[i] - mnew);
            float rs = 0.f;
            #pragma unroll
            for (int j = 0; j < 4; j++) { s[i][j] = __expf(s[i][j] - mnew); rs += s[i][j]; }
            #pragma unroll
            for (int off = 1; off < 16; off <<= 1)
                rs += __shfl_xor_sync(0xffffffffu, rs, off);
            lrow[i] = lrow[i] * corr + rs;
            mrow[i] = mnew;
            #pragma unroll
            for (int j = 0; j < 4; j++) o[i][j] *= corr;
        }

        // all K reads done -> reuse KP as transposed P tile
        __syncthreads();
        #pragma unroll
        for (int i = 0; i < 4; i++)
            #pragma unroll
            for (int j = 0; j < 4; j++)
                KP[tx*4 + j][ty*4 + i] = s[i][j];
        __syncthreads();

        // O += P V
        #pragma unroll 16
        for (int kk = 0; kk < 64; kk++) {
            float4 a = *(float4*)&KP[kk][ty*4];
            float4 b = *(float4*)&Vs[kk][tx*4];
            float av[4] = {a.x, a.y, a.z, a.w};
            float bv[4] = {b.x, b.y, b.z, b.w};
            #pragma unroll
            for (int i = 0; i < 4; i++)
                #pragma unroll
                for (int j = 0; j < 4; j++)
                    o[i][j] += av[i] * bv[j];
        }
    }

    #pragma unroll
    for (int i = 0; i < 4; i++) {
        float inv = 1.0f / lrow[i];
        int t = qt*64 + ty*4 + i;
        float4 v4 = make_float4(o[i][0]*inv, o[i][1]*inv, o[i][2]*inv, o[i][3]*inv);
        *(float4*)(g_att + ((size_t)bh * NT + t) * HD + tx*4) = v4;
    }
}

// ---------------------------------------------------------------------------
// Kernel 3: output projection + bias. grid (NM/64, NC/64), block 256.
// out[m][e] = sum_c attn_concat[m][c] * Wp[c][e] + bp[e]
// K chunks of 64 == one head, so g_att reads stay coalesced.
// ---------------------------------------------------------------------------
__global__ __launch_bounds__(256) void proj_kernel(
    const float* __restrict__ Wp,
    const float* __restrict__ bp,
    float* __restrict__ out)
{
    __shared__ float YsT[64][68];
    __shared__ float Ws[64][68];

    int m0 = blockIdx.x * 64;
    int e0 = blockIdx.y * 64;
    int tid = threadIdx.x;
    int ty = tid >> 4, tx = tid & 15;
    int b  = m0 / NT;
    int t0 = m0 % NT;

    float acc[4][4] = {};

    for (int hc = 0; hc < NH; hc++) {
        __syncthreads();
        const float* ybase = g_att + ((size_t)(b*NH + hc)*NT + t0) * HD;
        #pragma unroll
        for (int i = 0; i < 4; i++) {
            int e = tid + i * 256;
            int r = e >> 4, c4 = (e & 15) * 4;
            float4 v4 = *(const float4*)(ybase + (size_t)r * HD + c4);
            YsT[c4+0][r] = v4.x; YsT[c4+1][r] = v4.y;
            YsT[c4+2][r] = v4.z; YsT[c4+3][r] = v4.w;
        }
        #pragma unroll
        for (int i = 0; i < 4; i++) {
            int e = tid + i * 256;
            int c = e >> 4, d4 = (e & 15) * 4;
            *(float4*)&Ws[c][d4] =
                *(const float4*)(Wp + (size_t)(hc*64 + c) * NC + e0 + d4);
        }
        __syncthreads();

        #pragma unroll 16
        for (int kk = 0; kk < 64; kk++) {
            float4 a = *(float4*)&YsT[kk][ty*4];
            float4 b4 = *(float4*)&Ws[kk][tx*4];
            float av[4] = {a.x, a.y, a.z, a.w};
            float bv[4] = {b4.x, b4.y, b4.z, b4.w};
            #pragma unroll
            for (int i = 0; i < 4; i++)
                #pragma unroll
                for (int j = 0; j < 4; j++)
                    acc[i][j] += av[i] * bv[j];
        }
    }

    float4 bb = *(const float4*)(bp + e0 + tx*4);
    #pragma unroll
    for (int i = 0; i < 4; i++) {
        int m = m0 + ty*4 + i;
        float4 v4 = make_float4(acc[i][0] + bb.x, acc[i][1] + bb.y,
                                acc[i][2] + bb.z, acc[i][3] + bb.w);
        *(float4*)(out + (size_t)m * NC + e0 + tx*4) = v4;
    }
}

// ---------------------------------------------------------------------------

extern "C" void kernel_launch(void* const* d_in, const int* in_sizes, int n_in,
                              void* d_out, int out_size)
{
    const float* x  = (const float*)d_in[0];
    const float* Wq = (const float*)d_in[1];
    const float* Wk = (const float*)d_in[2];
    const float* Wv = (const float*)d_in[3];
    const float* Wp = (const float*)d_in[4];
    const float* bp = (const float*)d_in[5];
    float* out = (float*)d_out;

    qkv_kernel<<<dim3(NM/64, 3*NH), 256>>>(x, Wq, Wk, Wv);
    attn_kernel<<<dim3(NT/64, NB*NH), 256>>>();
    proj_kernel<<<dim3(NM/64, NC/64), 256>>>(Wp, bp, out);
}

// round 3
// speedup vs baseline: 1.3584x; 1.3584x over previous
#include <cuda_runtime.h>

#define NC 384
#define NH 6
#define HD 64
#define NB 64
#define NT 256
#define NM (NB*NT)
#define SOFT_SCALE 0.125f

// scratch (allocation-free rule: __device__ globals)
__device__ float g_q[(size_t)NB*NH*NT*HD];
__device__ float g_k[(size_t)NB*NH*NT*HD];
__device__ float g_v[(size_t)NB*NH*NT*HD];
__device__ float g_att[(size_t)NB*NH*NT*HD];

// ===========================================================================
// Kernel 1: QKV projection. grid (NM/256, 3*NH), block 256.
// Block tile: M=256 (one batch row), N=64 (head dim), K=384 chunked by 32.
// Micro-tile 8x8 (thread grid ty=0..31 x tx=0..7) -> 4 LDS.128 per 64 FFMA.
// A^T staged swizzled: elem (k=c, m=r) at c*256 + (((r>>2) ^ ((c>>2)&7))<<2) + (r&3)
// ===========================================================================
__global__ __launch_bounds__(256) void qkv_kernel(
    const float* __restrict__ x,
    const float* __restrict__ Wq,
    const float* __restrict__ Wk,
    const float* __restrict__ Wv)
{
    __shared__ float AT[32*256];   // swizzled A^T (K x M)
    __shared__ float Bs[32*64];    // natural (K x N)

    int mat = blockIdx.y / NH;
    int h   = blockIdx.y % NH;
    const float* W = (mat == 0 ? Wq : (mat == 1 ? Wk : Wv)) + (size_t)h * NC * HD;
    float* outp = (mat == 0 ? g_q : (mat == 1 ? g_k : g_v));

    int b   = blockIdx.x;          // M tile == one batch row (NT=256)
    int tid = threadIdx.x;
    int ty = tid >> 3, tx = tid & 7;

    const float4* AT4 = (const float4*)AT;
    const float4* Bs4 = (const float4*)Bs;

    float acc[8][8] = {};

    for (int c0 = 0; c0 < NC; c0 += 32) {
        __syncthreads();
        // stage A^T (x tile 256 rows x 32 cols), swizzled, conflict-free stores
        #pragma unroll
        for (int s = 0; s < 8; s++) {
            int e = tid + s * 256;
            int r = e >> 3, cg = e & 7;
            float4 v4 = *(const float4*)(x + ((size_t)b * NT + r) * NC + c0 + cg * 4);
            int base = (cg * 4) * 256 + (((r >> 2) ^ cg) << 2) + (r & 3);
            AT[base          ] = v4.x;
            AT[base + 256    ] = v4.y;
            AT[base + 512    ] = v4.z;
            AT[base + 768    ] = v4.w;
        }
        // stage B (W rows c0..c0+32, all 64 cols), natural
        #pragma unroll
        for (int s = 0; s < 2; s++) {
            int e = tid + s * 256;
            int c = e >> 4, dg = e & 15;
            *(float4*)&Bs[c * 64 + dg * 4] =
                *(const float4*)(W + (size_t)(c0 + c) * HD + dg * 4);
        }
        __syncthreads();

        #pragma unroll 8
        for (int kk = 0; kk < 32; kk++) {
            int sw = (kk >> 2) & 7;
            float4 a0 = AT4[kk * 64 + ((ty * 2) ^ sw)];
            float4 a1 = AT4[kk * 64 + ((ty * 2 + 1) ^ sw)];
            float4 b0 = Bs4[kk * 16 + tx * 2];
            float4 b1 = Bs4[kk * 16 + tx * 2 + 1];
            float av[8] = {a0.x,a0.y,a0.z,a0.w,a1.x,a1.y,a1.z,a1.w};
            float bv[8] = {b0.x,b0.y,b0.z,b0.w,b1.x,b1.y,b1.z,b1.w};
            #pragma unroll
            for (int i = 0; i < 8; i++)
                #pragma unroll
                for (int j = 0; j < 8; j++)
                    acc[i][j] += av[i] * bv[j];
        }
    }

    #pragma unroll
    for (int i = 0; i < 8; i++) {
        int t = ty * 8 + i;
        float* orow = outp + ((size_t)(b * NH + h) * NT + t) * HD + tx * 8;
        *(float4*)(orow    ) = make_float4(acc[i][0], acc[i][1], acc[i][2], acc[i][3]);
        *(float4*)(orow + 4) = make_float4(acc[i][4], acc[i][5], acc[i][6], acc[i][7]);
    }
}

// ===========================================================================
// Kernel 2: causal flash attention. grid (NT/64, NB*NH), block 256, 4x4 micro.
// Swizzled transposed tiles (stride 64, XOR on float4 group):
//   elem (row c, col m) at c*64 + (((m>>2) ^ ((c>>2)&15))<<2) + (m&3)
// QsT: (d, m) of Q*scale ; KP: (d, s) of K, then reused as (s, m) of P^T ; Vs natural.
// ===========================================================================
__global__ __launch_bounds__(256) void attn_kernel()
{
    __shared__ float QsT[64*64];
    __shared__ float KP [64*64];
    __shared__ float Vs [64*64];

    int qt = blockIdx.x;
    int bh = blockIdx.y;
    const float* qbase = g_q + (size_t)bh * NT * HD;
    const float* kbase = g_k + (size_t)bh * NT * HD;
    const float* vbase = g_v + (size_t)bh * NT * HD;

    int tid = threadIdx.x;
    int ty = tid >> 4, tx = tid & 15;

    const float4* Q4 = (const float4*)QsT;
    const float4* K4 = (const float4*)KP;
    const float4* V4 = (const float4*)Vs;

    // load Q tile transposed + swizzled, pre-scaled by 1/8
    #pragma unroll
    for (int s = 0; s < 4; s++) {
        int e = tid + s * 256;
        int r = e >> 4, dg = e & 15;
        float4 v4 = *(const float4*)(qbase + (size_t)(qt*64 + r) * HD + dg * 4);
        int base = (dg * 4) * 64 + (((r >> 2) ^ dg) << 2) + (r & 3);
        QsT[base      ] = v4.x * SOFT_SCALE;
        QsT[base + 64 ] = v4.y * SOFT_SCALE;
        QsT[base + 128] = v4.z * SOFT_SCALE;
        QsT[base + 192] = v4.w * SOFT_SCALE;
    }

    float o[4][4] = {};
    float mrow[4] = {-1e30f, -1e30f, -1e30f, -1e30f};
    float lrow[4] = {};

    for (int st = 0; st <= qt; st++) {
        __syncthreads();   // Q visibility (iter 0), KP/Vs reuse (later iters)
        #pragma unroll
        for (int s = 0; s < 4; s++) {
            int e = tid + s * 256;
            int r = e >> 4, dg = e & 15;
            float4 kv = *(const float4*)(kbase + (size_t)(st*64 + r) * HD + dg * 4);
            int base = (dg * 4) * 64 + (((r >> 2) ^ dg) << 2) + (r & 3);
            KP[base      ] = kv.x;
            KP[base + 64 ] = kv.y;
            KP[base + 128] = kv.z;
            KP[base + 192] = kv.w;
            float4 vv = *(const float4*)(vbase + (size_t)(st*64 + r) * HD + dg * 4);
            *(float4*)&Vs[r * 64 + dg * 4] = vv;
        }
        __syncthreads();

        // S = (Q*scale) K^T
        float sacc[4][4] = {};
        #pragma unroll 8
        for (int kk = 0; kk < 64; kk++) {
            int sw = (kk >> 2) & 15;
            float4 a = Q4[kk * 16 + (ty ^ sw)];
            float4 bq = K4[kk * 16 + (tx ^ sw)];
            float av[4] = {a.x, a.y, a.z, a.w};
            float bv[4] = {bq.x, bq.y, bq.z, bq.w};
            #pragma unroll
            for (int i = 0; i < 4; i++)
                #pragma unroll
                for (int j = 0; j < 4; j++)
                    sacc[i][j] += av[i] * bv[j];
        }

        // causal mask (only diagonal tile)
        if (st == qt) {
            #pragma unroll
            for (int i = 0; i < 4; i++) {
                int rg = ty*4 + i;
                #pragma unroll
                for (int j = 0; j < 4; j++)
                    if (tx*4 + j > rg) sacc[i][j] = -1e30f;
            }
        }

        // online softmax; rows reduced across the 16 tx lanes
        #pragma unroll
        for (int i = 0; i < 4; i++) {
            float mx = fmaxf(fmaxf(sacc[i][0], sacc[i][1]), fmaxf(sacc[i][2], sacc[i][3]));
            #pragma unroll
            for (int off = 1; off < 16; off <<= 1)
                mx = fmaxf(mx, __shfl_xor_sync(0xffffffffu, mx, off));
            float mnew = fmaxf(mrow[i], mx);
            float corr = __expf(mrow[i] - mnew);
            float rs = 0.f;
            #pragma unroll
            for (int j = 0; j < 4; j++) { sacc[i][j] = __expf(sacc[i][j] - mnew); rs += sacc[i][j]; }
            #pragma unroll
            for (int off = 1; off < 16; off <<= 1)
                rs += __shfl_xor_sync(0xffffffffu, rs, off);
            lrow[i] = lrow[i] * corr + rs;
            mrow[i] = mnew;
            #pragma unroll
            for (int j = 0; j < 4; j++) o[i][j] *= corr;
        }

        // K reads done -> store P^T into KP, swizzled: (s=tx*4+j, m=ty*4+i)
        __syncthreads();
        #pragma unroll
        for (int j = 0; j < 4; j++) {
            int base = (tx*4 + j) * 64 + ((ty ^ tx) << 2);
            #pragma unroll
            for (int i = 0; i < 4; i++)
                KP[base + i] = sacc[i][j];
        }
        __syncthreads();

        // O += P V
        #pragma unroll 8
        for (int kk = 0; kk < 64; kk++) {
            int sw = (kk >> 2) & 15;
            float4 a = K4[kk * 16 + (ty ^ sw)];
            float4 bv4 = V4[kk * 16 + tx];
            float av[4] = {a.x, a.y, a.z, a.w};
            float bv[4] = {bv4.x, bv4.y, bv4.z, bv4.w};
            #pragma unroll
            for (int i = 0; i < 4; i++)
                #pragma unroll
                for (int j = 0; j < 4; j++)
                    o[i][j] += av[i] * bv[j];
        }
    }

    #pragma unroll
    for (int i = 0; i < 4; i++) {
        float inv = 1.0f / lrow[i];
        int t = qt*64 + ty*4 + i;
        float4 v4 = make_float4(o[i][0]*inv, o[i][1]*inv, o[i][2]*inv, o[i][3]*inv);
        *(float4*)(g_att + ((size_t)bh * NT + t) * HD + tx*4) = v4;
    }
}

// ===========================================================================
// Kernel 3: output projection + bias. grid (NM/256, NC/64), block 256.
// Block tile: M=256 (one batch row), N=64, K=384 chunked by 32 (half-head).
// Same 8x8 micro-tile + swizzled A^T as qkv_kernel.
// ===========================================================================
__global__ __launch_bounds__(256) void proj_kernel(
    const float* __restrict__ Wp,
    const float* __restrict__ bp,
    float* __restrict__ out)
{
    __shared__ float AT[32*256];
    __shared__ float Bs[32*64];

    int b  = blockIdx.x;
    int e0 = blockIdx.y * 64;
    int tid = threadIdx.x;
    int ty = tid >> 3, tx = tid & 7;

    const float4* AT4 = (const float4*)AT;
    const float4* Bs4 = (const float4*)Bs;

    float acc[8][8] = {};

    for (int cc = 0; cc < 12; cc++) {          // 12 chunks of 32 over K=384
        int hc = cc >> 1;
        int dblk = (cc & 1) * 32;
        const float* ybase = g_att + (size_t)(b * NH + hc) * NT * HD + dblk;
        __syncthreads();
        #pragma unroll
        for (int s = 0; s < 8; s++) {
            int e = tid + s * 256;
            int r = e >> 3, cg = e & 7;
            float4 v4 = *(const float4*)(ybase + (size_t)r * HD + cg * 4);
            int base = (cg * 4) * 256 + (((r >> 2) ^ cg) << 2) + (r & 3);
            AT[base      ] = v4.x;
            AT[base + 256] = v4.y;
            AT[base + 512] = v4.z;
            AT[base + 768] = v4.w;
        }
        #pragma unroll
        for (int s = 0; s < 2; s++) {
            int e = tid + s * 256;
            int c = e >> 4, eg = e & 15;
            *(float4*)&Bs[c * 64 + eg * 4] =
                *(const float4*)(Wp + (size_t)(cc * 32 + c) * NC + e0 + eg * 4);
        }
        __syncthreads();

        #pragma unroll 8
        for (int kk = 0; kk < 32; kk++) {
            int sw = (kk >> 2) & 7;
            float4 a0 = AT4[kk * 64 + ((ty * 2) ^ sw)];
            float4 a1 = AT4[kk * 64 + ((ty * 2 + 1) ^ sw)];
            float4 b0 = Bs4[kk * 16 + tx * 2];
            float4 b1 = Bs4[kk * 16 + tx * 2 + 1];
            float av[8] = {a0.x,a0.y,a0.z,a0.w,a1.x,a1.y,a1.z,a1.w};
            float bv[8] = {b0.x,b0.y,b0.z,b0.w,b1.x,b1.y,b1.z,b1.w};
            #pragma unroll
            for (int i = 0; i < 8; i++)
                #pragma unroll
                for (int j = 0; j < 8; j++)
                    acc[i][j] += av[i] * bv[j];
        }
    }

    float4 bb0 = *(const float4*)(bp + e0 + tx*8);
    float4 bb1 = *(const float4*)(bp + e0 + tx*8 + 4);
    #pragma unroll
    for (int i = 0; i < 8; i++) {
        int m = b * NT + ty * 8 + i;
        float* orow = out + (size_t)m * NC + e0 + tx * 8;
        *(float4*)(orow    ) = make_float4(acc[i][0]+bb0.x, acc[i][1]+bb0.y,
                                           acc[i][2]+bb0.z, acc[i][3]+bb0.w);
        *(float4*)(orow + 4) = make_float4(acc[i][4]+bb1.x, acc[i][5]+bb1.y,
                                           acc[i][6]+bb1.z, acc[i][7]+bb1.w);
    }
}

// ---------------------------------------------------------------------------

extern "C" void kernel_launch(void* const* d_in, const int* in_sizes, int n_in,
                              void* d_out, int out_size)
{
    const float* x  = (const float*)d_in[0];
    const float* Wq = (const float*)d_in[1];
    const float* Wk = (const float*)d_in[2];
    const float* Wv = (const float*)d_in[3];
    const float* Wp = (const float*)d_in[4];
    const float* bp = (const float*)d_in[5];
    float* out = (float*)d_out;

    qkv_kernel<<<dim3(NM/256, 3*NH), 256>>>(x, Wq, Wk, Wv);
    attn_kernel<<<dim3(NT/64, NB*NH), 256>>>();
    proj_kernel<<<dim3(NM/256, NC/64), 256>>>(Wp, bp, out);
}

// round 6
// speedup vs baseline: 2.6281x; 1.9348x over previous
#include <cuda_runtime.h>
#include <cuda_fp16.h>
#include <cstdint>

#define NC 384
#define NH 6
#define HD 64
#define NB 64
#define NT 256
#define NM (NB*NT)
#define SOFT_SCALE 0.125f

// scratch (allocation-free rule: __device__ globals)
__device__ float g_q[(size_t)NB*NH*NT*HD];
__device__ float g_k[(size_t)NB*NH*NT*HD];
__device__ float g_v[(size_t)NB*NH*NT*HD];
__device__ float g_att[(size_t)NB*NH*NT*HD];

// SW128 swizzle on byte offsets (XOR bits [6:4] with bits [9:7])
#define SWZ128(b) ((b) ^ (((b) >> 3) & 0x70))

static __device__ __forceinline__ uint32_t smem_u32(const void* p) {
    uint32_t a;
    asm("{ .reg .u64 t; cvta.to.shared.u64 t, %1; cvt.u32.u64 %0, t; }"
        : "=r"(a) : "l"(p));
    return a;
}

static __device__ __forceinline__ void ldsm_x4(
    uint32_t& r0, uint32_t& r1, uint32_t& r2, uint32_t& r3, uint32_t addr)
{
    asm volatile("ldmatrix.sync.aligned.m8n8.x4.shared.b16 {%0,%1,%2,%3}, [%4];"
                 : "=r"(r0), "=r"(r1), "=r"(r2), "=r"(r3) : "r"(addr));
}

static __device__ __forceinline__ void mma16816(
    float* c, uint32_t a0, uint32_t a1, uint32_t a2, uint32_t a3,
    uint32_t b0, uint32_t b1)
{
    asm volatile(
        "mma.sync.aligned.m16n8k16.row.col.f32.f16.f16.f32 "
        "{%0,%1,%2,%3}, {%4,%5,%6,%7}, {%8,%9}, {%0,%1,%2,%3};"
        : "+f"(c[0]), "+f"(c[1]), "+f"(c[2]), "+f"(c[3])
        : "r"(a0), "r"(a1), "r"(a2), "r"(a3), "r"(b0), "r"(b1));
}

static __device__ __forceinline__ uint32_t f2h2(float a, float b) {
    __half2 h = __floats2half2_rn(a, b);
    return *reinterpret_cast<uint32_t*>(&h);
}

// ===========================================================================
// Kernel 1: QKV projection via mma.sync HMMA.
// grid (NM/128, NH), block 384 (12 warps). CTA: 128 tokens x 1 head, 3 mats.
// Warp w: mat = w>>2, rowtile = w&3 (32 rows). Warp tile 32x64.
// smem: A [128m x 64k] fp16 SW128 rows(128B); B x3: [64n x 64k] fp16 SW128.
// ===========================================================================
__global__ __launch_bounds__(384) void qkv_tc_kernel(
    const float* __restrict__ x,
    const float* __restrict__ Wq,
    const float* __restrict__ Wk,
    const float* __restrict__ Wv)
{
    __shared__ __align__(1024) unsigned char smA[16384];
    __shared__ __align__(1024) unsigned char smB[3*8192];
    const uint32_t sA = smem_u32(smA);
    const uint32_t sB = smem_u32(smB);

    int tid = threadIdx.x;
    int wid = tid >> 5, lane = tid & 31;
    int mat = wid >> 2, rt = wid & 3;
    int h  = blockIdx.y;
    int m0 = blockIdx.x * 128;

    const float* Wmats[3] = {Wq + (size_t)h * NC * HD,
                             Wk + (size_t)h * NC * HD,
                             Wv + (size_t)h * NC * HD};

    float acc[2][8][4] = {};

    for (int c = 0; c < 6; c++) {
        int c0 = c * 64;
        __syncthreads();
        // stage A: x[m0+r][c0 + cg*8 ..] -> fp16 SW128 (16B stores)
        for (int e = tid; e < 1024; e += 384) {
            int r = e >> 3, cg = e & 7;
            const float* p = x + (size_t)(m0 + r) * NC + c0 + cg * 8;
            float4 u = *(const float4*)(p);
            float4 v = *(const float4*)(p + 4);
            uint4 w = make_uint4(f2h2(u.x,u.y), f2h2(u.z,u.w),
                                 f2h2(v.x,v.y), f2h2(v.z,v.w));
            *(uint4*)(smA + SWZ128(r * 128 + cg * 16)) = w;
        }
        // stage B: B[n][k] = W[c0+k][n]; one 8B store per item
        for (int e = tid; e < 3072; e += 384) {
            int mt = e >> 10, rem = e & 1023;
            int n = rem & 63, kg = rem >> 6;      // kg 0..15 (4 k each)
            const float* wp = Wmats[mt] + (size_t)(c0 + kg * 4) * HD + n;
            float w0 = wp[0], w1 = wp[HD], w2 = wp[2*HD], w3 = wp[3*HD];
            uint2 pk = make_uint2(f2h2(w0, w1), f2h2(w2, w3));
            *(uint2*)(smB + mt * 8192 + SWZ128(n * 128 + kg * 8)) = pk;
        }
        __syncthreads();

        uint32_t bbase = sB + mat * 8192;
        #pragma unroll
        for (int ks = 0; ks < 4; ks++) {
            int col16 = ks * 2 + (lane >> 4);
            // A frags: 2 m-blocks of 16
            uint32_t a[2][4];
            #pragma unroll
            for (int mb = 0; mb < 2; mb++) {
                int row = rt * 32 + mb * 16 + (lane & 15);
                uint32_t addr = sA + SWZ128(row * 128 + col16 * 16);
                ldsm_x4(a[mb][0], a[mb][1], a[mb][2], a[mb][3], addr);
            }
            // B frags: 8 n-blocks of 8 (pairs via x4)
            uint32_t b[8][2];
            #pragma unroll
            for (int np = 0; np < 4; np++) {
                int n = np * 16 + (lane & 15);
                uint32_t addr = bbase + SWZ128(n * 128 + col16 * 16);
                ldsm_x4(b[np*2][0], b[np*2+1][0], b[np*2][1], b[np*2+1][1], addr);
            }
            #pragma unroll
            for (int mb = 0; mb < 2; mb++)
                #pragma unroll
                for (int nb = 0; nb < 8; nb++)
                    mma16816(acc[mb][nb], a[mb][0], a[mb][1], a[mb][2], a[mb][3],
                             b[nb][0], b[nb][1]);
        }
    }

    // epilogue: write fp32 q/k/v in [B,H,T,D]
    float* const outs3[3] = {g_q, g_k, g_v};
    float* outp = outs3[mat];
    #pragma unroll
    for (int mb = 0; mb < 2; mb++) {
        int m_global = m0 + rt * 32 + mb * 16 + (lane >> 2);
        int b = m_global >> 8, t = m_global & 255;
        float* orow0 = outp + ((size_t)(b * NH + h) * NT + t) * HD;
        float* orow1 = outp + ((size_t)(b * NH + h) * NT + t + 8) * HD;
        #pragma unroll
        for (int nb = 0; nb < 8; nb++) {
            int n = nb * 8 + (lane & 3) * 2;
            *(float2*)(orow0 + n) = make_float2(acc[mb][nb][0], acc[mb][nb][1]);
            *(float2*)(orow1 + n) = make_float2(acc[mb][nb][2], acc[mb][nb][3]);
        }
    }
}

// ===========================================================================
// Kernel 2: causal flash attention (fp32, unchanged from R3 passing version).
// ===========================================================================
__global__ __launch_bounds__(256) void attn_kernel()
{
    __shared__ float QsT[64*64];
    __shared__ float KP [64*64];
    __shared__ float Vs [64*64];

    int qt = blockIdx.x;
    int bh = blockIdx.y;
    const float* qbase = g_q + (size_t)bh * NT * HD;
    const float* kbase = g_k + (size_t)bh * NT * HD;
    const float* vbase = g_v + (size_t)bh * NT * HD;

    int tid = threadIdx.x;
    int ty = tid >> 4, tx = tid & 15;

    const float4* Q4 = (const float4*)QsT;
    const float4* K4 = (const float4*)KP;
    const float4* V4 = (const float4*)Vs;

    #pragma unroll
    for (int s = 0; s < 4; s++) {
        int e = tid + s * 256;
        int r = e >> 4, dg = e & 15;
        float4 v4 = *(const float4*)(qbase + (size_t)(qt*64 + r) * HD + dg * 4);
        int base = (dg * 4) * 64 + (((r >> 2) ^ dg) << 2) + (r & 3);
        QsT[base      ] = v4.x * SOFT_SCALE;
        QsT[base + 64 ] = v4.y * SOFT_SCALE;
        QsT[base + 128] = v4.z * SOFT_SCALE;
        QsT[base + 192] = v4.w * SOFT_SCALE;
    }

    float o[4][4] = {};
    float mrow[4] = {-1e30f, -1e30f, -1e30f, -1e30f};
    float lrow[4] = {};

    for (int st = 0; st <= qt; st++) {
        __syncthreads();
        #pragma unroll
        for (int s = 0; s < 4; s++) {
            int e = tid + s * 256;
            int r = e >> 4, dg = e & 15;
            float4 kv = *(const float4*)(kbase + (size_t)(st*64 + r) * HD + dg * 4);
            int base = (dg * 4) * 64 + (((r >> 2) ^ dg) << 2) + (r & 3);
            KP[base      ] = kv.x;
            KP[base + 64 ] = kv.y;
            KP[base + 128] = kv.z;
            KP[base + 192] = kv.w;
            float4 vv = *(const float4*)(vbase + (size_t)(st*64 + r) * HD + dg * 4);
            *(float4*)&Vs[r * 64 + dg * 4] = vv;
        }
        __syncthreads();

        float sacc[4][4] = {};
        #pragma unroll 8
        for (int kk = 0; kk < 64; kk++) {
            int sw = (kk >> 2) & 15;
            float4 a = Q4[kk * 16 + (ty ^ sw)];
            float4 bq = K4[kk * 16 + (tx ^ sw)];
            float av[4] = {a.x, a.y, a.z, a.w};
            float bv[4] = {bq.x, bq.y, bq.z, bq.w};
            #pragma unroll
            for (int i = 0; i < 4; i++)
                #pragma unroll
                for (int j = 0; j < 4; j++)
                    sacc[i][j] += av[i] * bv[j];
        }

        if (st == qt) {
            #pragma unroll
            for (int i = 0; i < 4; i++) {
                int rg = ty*4 + i;
                #pragma unroll
                for (int j = 0; j < 4; j++)
                    if (tx*4 + j > rg) sacc[i][j] = -1e30f;
            }
        }

        #pragma unroll
        for (int i = 0; i < 4; i++) {
            float mx = fmaxf(fmaxf(sacc[i][0], sacc[i][1]), fmaxf(sacc[i][2], sacc[i][3]));
            #pragma unroll
            for (int off = 1; off < 16; off <<= 1)
                mx = fmaxf(mx, __shfl_xor_sync(0xffffffffu, mx, off));
            float mnew = fmaxf(mrow[i], mx);
            float corr = __expf(mrow[i] - mnew);
            float rs = 0.f;
            #pragma unroll
            for (int j = 0; j < 4; j++) { sacc[i][j] = __expf(sacc[i][j] - mnew); rs += sacc[i][j]; }
            #pragma unroll
            for (int off = 1; off < 16; off <<= 1)
                rs += __shfl_xor_sync(0xffffffffu, rs, off);
            lrow[i] = lrow[i] * corr + rs;
            mrow[i] = mnew;
            #pragma unroll
            for (int j = 0; j < 4; j++) o[i][j] *= corr;
        }

        __syncthreads();
        #pragma unroll
        for (int j = 0; j < 4; j++) {
            int base = (tx*4 + j) * 64 + ((ty ^ tx) << 2);
            #pragma unroll
            for (int i = 0; i < 4; i++)
                KP[base + i] = sacc[i][j];
        }
        __syncthreads();

        #pragma unroll 8
        for (int kk = 0; kk < 64; kk++) {
            int sw = (kk >> 2) & 15;
            float4 a = K4[kk * 16 + (ty ^ sw)];
            float4 bv4 = V4[kk * 16 + tx];
            float av[4] = {a.x, a.y, a.z, a.w};
            float bv[4] = {bv4.x, bv4.y, bv4.z, bv4.w};
            #pragma unroll
            for (int i = 0; i < 4; i++)
                #pragma unroll
                for (int j = 0; j < 4; j++)
                    o[i][j] += av[i] * bv[j];
        }
    }

    #pragma unroll
    for (int i = 0; i < 4; i++) {
        float inv = 1.0f / lrow[i];
        int t = qt*64 + ty*4 + i;
        float4 v4 = make_float4(o[i][0]*inv, o[i][1]*inv, o[i][2]*inv, o[i][3]*inv);
        *(float4*)(g_att + ((size_t)bh * NT + t) * HD + tx*4) = v4;
    }
}

// ===========================================================================
// Kernel 3: output projection + bias via mma.sync HMMA.
// grid (NM/128, NC/64), block 256 (8 warps). Warp tile 32x32 (rt=w&3, ct=w>>2).
// K chunks of 64 == one head.
// ===========================================================================
__global__ __launch_bounds__(256) void proj_tc_kernel(
    const float* __restrict__ Wp,
    const float* __restrict__ bp,
    float* __restrict__ out)
{
    __shared__ __align__(1024) unsigned char smA[16384];
    __shared__ __align__(1024) unsigned char smB[8192];
    const uint32_t sA = smem_u32(smA);
    const uint32_t sB = smem_u32(smB);

    int tid = threadIdx.x;
    int wid = tid >> 5, lane = tid & 31;
    int rt = wid & 3, ct = wid >> 2;
    int m0 = blockIdx.x * 128;
    int e0 = blockIdx.y * 64;
    int b  = m0 >> 8;
    int t0 = m0 & 255;

    float acc[2][4][4] = {};

    for (int hc = 0; hc < 6; hc++) {
        __syncthreads();
        const float* abase = g_att + (size_t)(b * NH + hc) * NT * HD + (size_t)t0 * HD;
        #pragma unroll
        for (int s = 0; s < 4; s++) {
            int e = tid + s * 256;
            int r = e >> 3, cg = e & 7;
            const float* p = abase + (size_t)r * HD + cg * 8;
            float4 u = *(const float4*)(p);
            float4 v = *(const float4*)(p + 4);
            uint4 w = make_uint4(f2h2(u.x,u.y), f2h2(u.z,u.w),
                                 f2h2(v.x,v.y), f2h2(v.z,v.w));
            *(uint4*)(smA + SWZ128(r * 128 + cg * 16)) = w;
        }
        #pragma unroll
        for (int s = 0; s < 4; s++) {
            int e = tid + s * 256;
            int n = e & 63, kg = e >> 6;
            const float* wp = Wp + (size_t)(hc * 64 + kg * 4) * NC + e0 + n;
            float w0 = wp[0], w1 = wp[NC], w2 = wp[2*NC], w3 = wp[3*NC];
            uint2 pk = make_uint2(f2h2(w0, w1), f2h2(w2, w3));
            *(uint2*)(smB + SWZ128(n * 128 + kg * 8)) = pk;
        }
        __syncthreads();

        #pragma unroll
        for (int ks = 0; ks < 4; ks++) {
            int col16 = ks * 2 + (lane >> 4);
            uint32_t a[2][4];
            #pragma unroll
            for (int mb = 0; mb < 2; mb++) {
                int row = rt * 32 + mb * 16 + (lane & 15);
                uint32_t addr = sA + SWZ128(row * 128 + col16 * 16);
                ldsm_x4(a[mb][0], a[mb][1], a[mb][2], a[mb][3], addr);
            }
            uint32_t bfr[4][2];
            #pragma unroll
            for (int np = 0; np < 2; np++) {
                int n = ct * 32 + np * 16 + (lane & 15);
                uint32_t addr = sB + SWZ128(n * 128 + col16 * 16);
                ldsm_x4(bfr[np*2][0], bfr[np*2+1][0], bfr[np*2][1], bfr[np*2+1][1], addr);
            }
            #pragma unroll
            for (int mb = 0; mb < 2; mb++)
                #pragma unroll
                for (int nb = 0; nb < 4; nb++)
                    mma16816(acc[mb][nb], a[mb][0], a[mb][1], a[mb][2], a[mb][3],
                             bfr[nb][0], bfr[nb][1]);
        }
    }

    #pragma unroll
    for (int mb = 0; mb < 2; mb++) {
        int m_global = m0 + rt * 32 + mb * 16 + (lane >> 2);
        float* orow0 = out + (size_t)m_global * NC;
        float* orow1 = out + (size_t)(m_global + 8) * NC;
        #pragma unroll
        for (int nb = 0; nb < 4; nb++) {
            int n = e0 + ct * 32 + nb * 8 + (lane & 3) * 2;
            float2 bb = *(const float2*)(bp + n);
            *(float2*)(orow0 + n) = make_float2(acc[mb][nb][0] + bb.x,
                                                acc[mb][nb][1] + bb.y);
            *(float2*)(orow1 + n) = make_float2(acc[mb][nb][2] + bb.x,
                                                acc[mb][nb][3] + bb.y);
        }
    }
}

// ---------------------------------------------------------------------------

extern "C" void kernel_launch(void* const* d_in, const int* in_sizes, int n_in,
                              void* d_out, int out_size)
{
    const float* x  = (const float*)d_in[0];
    const float* Wq = (const float*)d_in[1];
    const float* Wk = (const float*)d_in[2];
    const float* Wv = (const float*)d_in[3];
    const float* Wp = (const float*)d_in[4];
    const float* bp = (const float*)d_in[5];
    float* out = (float*)d_out;

    qkv_tc_kernel<<<dim3(NM/128, NH), 384>>>(x, Wq, Wk, Wv);
    attn_kernel<<<dim3(NT/64, NB*NH), 256>>>();
    proj_tc_kernel<<<dim3(NM/128, NC/64), 256>>>(Wp, bp, out);
}

// round 7
// speedup vs baseline: 3.9700x; 1.5106x over previous
#include <cuda_runtime.h>
#include <cuda_fp16.h>
#include <cstdint>

#define NC 384
#define NH 6
#define HD 64
#define NB 64
#define NT 256
#define NM (NB*NT)
#define SOFT_SCALE 0.125f

// fp16 scratch (allocation-free rule: __device__ globals)
__device__ __align__(128) __half g_x16[(size_t)NM*NC];
__device__ __align__(128) __half g_wqkv16[(size_t)3*NH*HD*NC];  // [mat*6+h][n=64][k=384]
__device__ __align__(128) __half g_wp16[(size_t)NC*NC];         // [n=384][k=384]
__device__ __align__(128) __half g_q16[(size_t)NB*NH*NT*HD];
__device__ __align__(128) __half g_k16[(size_t)NB*NH*NT*HD];
__device__ __align__(128) __half g_v16[(size_t)NB*NH*NT*HD];
__device__ __align__(128) __half g_att16[(size_t)NB*NH*NT*HD];

#define SWZ128(b) ((b) ^ (((b) >> 3) & 0x70))

static __device__ __forceinline__ uint32_t smem_u32(const void* p) {
    uint32_t a;
    asm("{ .reg .u64 t; cvta.to.shared.u64 t, %1; cvt.u32.u64 %0, t; }"
        : "=r"(a) : "l"(p));
    return a;
}
static __device__ __forceinline__ void ldsm_x4(
    uint32_t& r0, uint32_t& r1, uint32_t& r2, uint32_t& r3, uint32_t addr)
{
    asm volatile("ldmatrix.sync.aligned.m8n8.x4.shared.b16 {%0,%1,%2,%3}, [%4];"
                 : "=r"(r0), "=r"(r1), "=r"(r2), "=r"(r3) : "r"(addr));
}
static __device__ __forceinline__ void ldsm_x4_t(
    uint32_t& r0, uint32_t& r1, uint32_t& r2, uint32_t& r3, uint32_t addr)
{
    asm volatile("ldmatrix.sync.aligned.m8n8.x4.trans.shared.b16 {%0,%1,%2,%3}, [%4];"
                 : "=r"(r0), "=r"(r1), "=r"(r2), "=r"(r3) : "r"(addr));
}
static __device__ __forceinline__ void mma16816(
    float* c, uint32_t a0, uint32_t a1, uint32_t a2, uint32_t a3,
    uint32_t b0, uint32_t b1)
{
    asm volatile(
        "mma.sync.aligned.m16n8k16.row.col.f32.f16.f16.f32 "
        "{%0,%1,%2,%3}, {%4,%5,%6,%7}, {%8,%9}, {%0,%1,%2,%3};"
        : "+f"(c[0]), "+f"(c[1]), "+f"(c[2]), "+f"(c[3])
        : "r"(a0), "r"(a1), "r"(a2), "r"(a3), "r"(b0), "r"(b1));
}
static __device__ __forceinline__ uint32_t f2h2(float a, float b) {
    __half2 h = __floats2half2_rn(a, b);
    return *reinterpret_cast<uint32_t*>(&h);
}
#define CP_ASYNC16(d, s) \
    asm volatile("cp.async.ca.shared.global [%0], [%1], 16;" :: "r"(d), "l"(s))
#define CP_COMMIT() asm volatile("cp.async.commit_group;" ::: "memory")
#define CP_WAIT0()  asm volatile("cp.async.wait_group 0;" ::: "memory")
#define CP_WAIT1()  asm volatile("cp.async.wait_group 1;" ::: "memory")

// ===========================================================================
// Prologue 1: x -> fp16. grid 3072, block 256, 8 elems/thread.
// ===========================================================================
__global__ __launch_bounds__(256) void convert_x_kernel(const float* __restrict__ x)
{
    size_t i = ((size_t)blockIdx.x * 256 + threadIdx.x) * 8;
    float4 u = *(const float4*)(x + i);
    float4 v = *(const float4*)(x + i + 4);
    *(uint4*)(g_x16 + i) = make_uint4(f2h2(u.x,u.y), f2h2(u.z,u.w),
                                      f2h2(v.x,v.y), f2h2(v.z,v.w));
}

// ===========================================================================
// Prologue 2: weights -> fp16, transposed to [n][k]. grid 24, block 256.
// blocks 0..17: qkv (mat=b/6, h=b%6); blocks 18..23: Wp n-tile of 64.
// ===========================================================================
__global__ __launch_bounds__(256) void convert_w_kernel(
    const float* __restrict__ Wq, const float* __restrict__ Wk,
    const float* __restrict__ Wv, const float* __restrict__ Wp)
{
    __shared__ __half tw[64 * 384];   // [n(64)][k(384)]
    int blk = blockIdx.x, tid = threadIdx.x;

    if (blk < 18) {
        const float* Wsrcs[3] = {Wq, Wk, Wv};
        const float* W = Wsrcs[blk / 6] + (size_t)(blk % 6) * NC * HD;
        for (int e = tid; e < 384 * 16; e += 256) {
            int k = e >> 4, n4 = e & 15;
            float4 w = *(const float4*)(W + (size_t)k * HD + n4 * 4);
            tw[(n4*4+0) * 384 + k] = __float2half_rn(w.x);
            tw[(n4*4+1) * 384 + k] = __float2half_rn(w.y);
            tw[(n4*4+2) * 384 + k] = __float2half_rn(w.z);
            tw[(n4*4+3) * 384 + k] = __float2half_rn(w.w);
        }
        __syncthreads();
        uint4* dst = (uint4*)(g_wqkv16 + (size_t)blk * 64 * 384);
        for (int e = tid; e < 64 * 48; e += 256)
            dst[e] = *(uint4*)(tw + e * 8);
    } else {
        int n0 = (blk - 18) * 64;
        for (int e = tid; e < 384 * 16; e += 256) {
            int k = e >> 4, n4 = e & 15;
            float4 w = *(const float4*)(Wp + (size_t)k * NC + n0 + n4 * 4);
            tw[(n4*4+0) * 384 + k] = __float2half_rn(w.x);
            tw[(n4*4+1) * 384 + k] = __float2half_rn(w.y);
            tw[(n4*4+2) * 384 + k] = __float2half_rn(w.z);
            tw[(n4*4+3) * 384 + k] = __float2half_rn(w.w);
        }
        __syncthreads();
        uint4* dst = (uint4*)(g_wp16 + (size_t)n0 * 384);
        for (int e = tid; e < 64 * 48; e += 256)
            dst[e] = *(uint4*)(tw + e * 8);
    }
}

// ===========================================================================
// Kernel 1: QKV GEMM. grid (128, 18): 128-token m-tile x (mat,head) n=64.
// block 256 (8 warps): warp tile 32m x 32n. cp.async double-buffered K=6x64.
// ===========================================================================
__global__ __launch_bounds__(256) void qkv_tc_kernel()
{
    __shared__ __align__(1024) __half smA[2][128*64];
    __shared__ __align__(1024) __half smB[2][64*64];

    int tid = threadIdx.x;
    int wid = tid >> 5, lane = tid & 31;
    int rt = wid & 3, ct = wid >> 2;
    int mh = blockIdx.y;
    int m0 = blockIdx.x * 128;

    const uint32_t sAu[2] = {smem_u32(smA[0]), smem_u32(smA[1])};
    const uint32_t sBu[2] = {smem_u32(smB[0]), smem_u32(smB[1])};
    const __half* wsrc = g_wqkv16 + (size_t)mh * 64 * 384;

    float acc[2][4][4] = {};

    auto issue = [&](int c) {
        int c0 = c * 64, bf = c & 1;
        #pragma unroll
        for (int i = 0; i < 4; i++) {
            int e = tid + i * 256;
            int r = e >> 3, g = e & 7;
            CP_ASYNC16(sAu[bf] + SWZ128(r * 128 + g * 16),
                       g_x16 + (size_t)(m0 + r) * NC + c0 + g * 8);
        }
        #pragma unroll
        for (int i = 0; i < 2; i++) {
            int e = tid + i * 256;
            int n = e >> 3, g = e & 7;
            CP_ASYNC16(sBu[bf] + SWZ128(n * 128 + g * 16),
                       wsrc + (size_t)n * 384 + c0 + g * 8);
        }
    };

    issue(0); CP_COMMIT();
    for (int c = 0; c < 6; c++) {
        if (c < 5) { issue(c + 1); CP_COMMIT(); CP_WAIT1(); }
        else       { CP_WAIT0(); }
        __syncthreads();
        int bf = c & 1;
        #pragma unroll
        for (int ks = 0; ks < 4; ks++) {
            int col16 = ks * 2 + (lane >> 4);
            uint32_t a[2][4];
            #pragma unroll
            for (int mb = 0; mb < 2; mb++) {
                int row = rt * 32 + mb * 16 + (lane & 15);
                ldsm_x4(a[mb][0], a[mb][1], a[mb][2], a[mb][3],
                        sAu[bf] + SWZ128(row * 128 + col16 * 16));
            }
            uint32_t b[4][2];
            #pragma unroll
            for (int np = 0; np < 2; np++) {
                int n = ct * 32 + np * 16 + (lane & 15);
                ldsm_x4(b[np*2][0], b[np*2+1][0], b[np*2][1], b[np*2+1][1],
                        sBu[bf] + SWZ128(n * 128 + col16 * 16));
            }
            #pragma unroll
            for (int mb = 0; mb < 2; mb++)
                #pragma unroll
                for (int nb = 0; nb < 4; nb++)
                    mma16816(acc[mb][nb], a[mb][0], a[mb][1], a[mb][2], a[mb][3],
                             b[nb][0], b[nb][1]);
        }
        __syncthreads();
    }

    __half* const outs3[3] = {g_q16, g_k16, g_v16};
    __half* outp = outs3[mh / 6];
    int h = mh % 6;
    #pragma unroll
    for (int mb = 0; mb < 2; mb++) {
        int mg = m0 + rt * 32 + mb * 16 + (lane >> 2);
        int b = mg >> 8, t = mg & 255;
        __half* orow = outp + ((size_t)(b * NH + h) * NT + t) * HD;
        #pragma unroll
        for (int nb = 0; nb < 4; nb++) {
            int n = ct * 32 + nb * 8 + (lane & 3) * 2;
            *(uint32_t*)(orow + n)          = f2h2(acc[mb][nb][0], acc[mb][nb][1]);
            *(uint32_t*)(orow + 8*HD + n)   = f2h2(acc[mb][nb][2], acc[mb][nb][3]);
        }
    }
}

// ===========================================================================
// Kernel 2: causal flash attention via HMMA. grid (4 qt, 384 bh), block 128.
// Warp owns 16 q-rows. S C-frags reused in registers as P A-frags (FA2).
// ===========================================================================
__global__ __launch_bounds__(128) void attn_tc_kernel()
{
    __shared__ __align__(1024) __half smQ[64*64];
    __shared__ __align__(1024) __half smK[2][64*64];
    __shared__ __align__(1024) __half smV[2][64*64];

    int tid = threadIdx.x;
    int wid = tid >> 5, lane = tid & 31;
    int qt = blockIdx.x;
    int bh = blockIdx.y;

    const uint32_t sQu = smem_u32(smQ);
    const uint32_t sKu[2] = {smem_u32(smK[0]), smem_u32(smK[1])};
    const uint32_t sVu[2] = {smem_u32(smV[0]), smem_u32(smV[1])};
    const __half* qbase = g_q16 + (size_t)bh * NT * HD;
    const __half* kbase = g_k16 + (size_t)bh * NT * HD;
    const __half* vbase = g_v16 + (size_t)bh * NT * HD;

    // Q tile (64x64) once
    #pragma unroll
    for (int i = 0; i < 4; i++) {
        int e = tid + i * 128;
        int r = e >> 3, g = e & 7;
        CP_ASYNC16(sQu + SWZ128(r * 128 + g * 16),
                   qbase + (size_t)(qt*64 + r) * HD + g * 8);
    }
    auto issueKV = [&](int st) {
        int bf = st & 1;
        #pragma unroll
        for (int i = 0; i < 4; i++) {
            int e = tid + i * 128;
            int r = e >> 3, g = e & 7;
            CP_ASYNC16(sKu[bf] + SWZ128(r * 128 + g * 16),
                       kbase + (size_t)(st*64 + r) * HD + g * 8);
            CP_ASYNC16(sVu[bf] + SWZ128(r * 128 + g * 16),
                       vbase + (size_t)(st*64 + r) * HD + g * 8);
        }
    };
    issueKV(0); CP_COMMIT();

    float o[8][4] = {};
    float mrow[2] = {-1e30f, -1e30f};
    float lrow[2] = {};

    for (int st = 0; st <= qt; st++) {
        if (st < qt) { issueKV(st + 1); CP_COMMIT(); CP_WAIT1(); }
        else         { CP_WAIT0(); }
        __syncthreads();
        int bf = st & 1;

        // ---- S = Q K^T (16 rows per warp x 64 cols) ----
        float sacc[8][4] = {};
        #pragma unroll
        for (int ks = 0; ks < 4; ks++) {
            int col16 = ks * 2 + (lane >> 4);
            uint32_t a0, a1, a2, a3;
            {
                int row = wid * 16 + (lane & 15);
                ldsm_x4(a0, a1, a2, a3, sQu + SWZ128(row * 128 + col16 * 16));
            }
            uint32_t b[8][2];
            #pragma unroll
            for (int np = 0; np < 4; np++) {
                int n = np * 16 + (lane & 15);
                ldsm_x4(b[np*2][0], b[np*2+1][0], b[np*2][1], b[np*2+1][1],
                        sKu[bf] + SWZ128(n * 128 + col16 * 16));
            }
            #pragma unroll
            for (int nb = 0; nb < 8; nb++)
                mma16816(sacc[nb], a0, a1, a2, a3, b[nb][0], b[nb][1]);
        }

        // ---- scale + causal mask ----
        #pragma unroll
        for (int nb = 0; nb < 8; nb++)
            #pragma unroll
            for (int j = 0; j < 4; j++)
                sacc[nb][j] *= SOFT_SCALE;
        if (st == qt) {
            int r0 = qt*64 + wid*16 + (lane >> 2);
            #pragma unroll
            for (int nb = 0; nb < 8; nb++) {
                int cg = st*64 + nb*8 + (lane & 3) * 2;
                if (cg     > r0    ) sacc[nb][0] = -1e30f;
                if (cg + 1 > r0    ) sacc[nb][1] = -1e30f;
                if (cg     > r0 + 8) sacc[nb][2] = -1e30f;
                if (cg + 1 > r0 + 8) sacc[nb][3] = -1e30f;
            }
        }

        // ---- online softmax (2 rows/thread, reduce over 4 lanes) ----
        #pragma unroll
        for (int hf = 0; hf < 2; hf++) {
            float mx = -1e30f;
            #pragma unroll
            for (int nb = 0; nb < 8; nb++)
                mx = fmaxf(mx, fmaxf(sacc[nb][hf*2], sacc[nb][hf*2+1]));
            mx = fmaxf(mx, __shfl_xor_sync(0xffffffffu, mx, 1));
            mx = fmaxf(mx, __shfl_xor_sync(0xffffffffu, mx, 2));
            float mnew = fmaxf(mrow[hf], mx);
            float corr = __expf(mrow[hf] - mnew);
            float rs = 0.f;
            #pragma unroll
            for (int nb = 0; nb < 8; nb++) {
                float p0 = __expf(sacc[nb][hf*2]   - mnew);
                float p1 = __expf(sacc[nb][hf*2+1] - mnew);
                sacc[nb][hf*2] = p0; sacc[nb][hf*2+1] = p1;
                rs += p0 + p1;
            }
            rs += __shfl_xor_sync(0xffffffffu, rs, 1);
            rs += __shfl_xor_sync(0xffffffffu, rs, 2);
            lrow[hf] = lrow[hf] * corr + rs;
            mrow[hf] = mnew;
            #pragma unroll
            for (int nb = 0; nb < 8; nb++) {
                o[nb][hf*2]   *= corr;
                o[nb][hf*2+1] *= corr;
            }
        }

        // ---- O += P V  (P from registers, V via ldmatrix.trans) ----
        #pragma unroll
        for (int ks = 0; ks < 4; ks++) {
            uint32_t pa0 = f2h2(sacc[ks*2  ][0], sacc[ks*2  ][1]);
            uint32_t pa1 = f2h2(sacc[ks*2  ][2], sacc[ks*2  ][3]);
            uint32_t pa2 = f2h2(sacc[ks*2+1][0], sacc[ks*2+1][1]);
            uint32_t pa3 = f2h2(sacc[ks*2+1][2], sacc[ks*2+1][3]);
            #pragma unroll
            for (int np = 0; np < 4; np++) {
                int m = lane >> 3;
                int row = ks * 16 + ((m & 1) << 3) + (lane & 7);
                int colb = (np * 16 + ((m & 2) << 2)) * 2;
                uint32_t v0, v1, v2, v3;
                ldsm_x4_t(v0, v1, v2, v3, sVu[bf] + SWZ128(row * 128 + colb));
                mma16816(o[np*2],   pa0, pa1, pa2, pa3, v0, v1);
                mma16816(o[np*2+1], pa0, pa1, pa2, pa3, v2, v3);
            }
        }
        __syncthreads();
    }

    // ---- epilogue: O/l -> g_att16 fp16 ----
    float inv0 = 1.0f / lrow[0], inv1 = 1.0f / lrow[1];
    int t0 = qt*64 + wid*16 + (lane >> 2);
    __half* ob = g_att16 + ((size_t)bh * NT + t0) * HD;
    #pragma unroll
    for (int nb = 0; nb < 8; nb++) {
        int n = nb*8 + (lane & 3) * 2;
        *(uint32_t*)(ob + n)        = f2h2(o[nb][0]*inv0, o[nb][1]*inv0);
        *(uint32_t*)(ob + 8*HD + n) = f2h2(o[nb][2]*inv1, o[nb][3]*inv1);
    }
}

// ===========================================================================
// Kernel 3: output projection + bias. grid (128, 6), block 256 (8 warps).
// Warp tile 32x32. K = 6 chunks of 64 (one head each), cp.async pipelined.
// ===========================================================================
__global__ __launch_bounds__(256) void proj_tc_kernel(
    const float* __restrict__ bp, float* __restrict__ out)
{
    __shared__ __align__(1024) __half smA[2][128*64];
    __shared__ __align__(1024) __half smB[2][64*64];

    int tid = threadIdx.x;
    int wid = tid >> 5, lane = tid & 31;
    int rt = wid & 3, ct = wid >> 2;
    int m0 = blockIdx.x * 128;
    int e0 = blockIdx.y * 64;
    int b  = m0 >> 8;
    int t0 = m0 & 255;

    const uint32_t sAu[2] = {smem_u32(smA[0]), smem_u32(smA[1])};
    const uint32_t sBu[2] = {smem_u32(smB[0]), smem_u32(smB[1])};

    float acc[2][4][4] = {};

    auto issue = [&](int hc) {
        int bf = hc & 1;
        const __half* abase = g_att16 + ((size_t)(b * NH + hc) * NT + t0) * HD;
        #pragma unroll
        for (int i = 0; i < 4; i++) {
            int e = tid + i * 256;
            int r = e >> 3, g = e & 7;
            CP_ASYNC16(sAu[bf] + SWZ128(r * 128 + g * 16),
                       abase + (size_t)r * HD + g * 8);
        }
        #pragma unroll
        for (int i = 0; i < 2; i++) {
            int e = tid + i * 256;
            int n = e >> 3, g = e & 7;
            CP_ASYNC16(sBu[bf] + SWZ128(n * 128 + g * 16),
                       g_wp16 + (size_t)(e0 + n) * 384 + hc * 64 + g * 8);
        }
    };

    issue(0); CP_COMMIT();
    for (int hc = 0; hc < 6; hc++) {
        if (hc < 5) { issue(hc + 1); CP_COMMIT(); CP_WAIT1(); }
        else        { CP_WAIT0(); }
        __syncthreads();
        int bf = hc & 1;
        #pragma unroll
        for (int ks = 0; ks < 4; ks++) {
            int col16 = ks * 2 + (lane >> 4);
            uint32_t a[2][4];
            #pragma unroll
            for (int mb = 0; mb < 2; mb++) {
                int row = rt * 32 + mb * 16 + (lane & 15);
                ldsm_x4(a[mb][0], a[mb][1], a[mb][2], a[mb][3],
                        sAu[bf] + SWZ128(row * 128 + col16 * 16));
            }
            uint32_t bb[4][2];
            #pragma unroll
            for (int np = 0; np < 2; np++) {
                int n = ct * 32 + np * 16 + (lane & 15);
                ldsm_x4(bb[np*2][0], bb[np*2+1][0], bb[np*2][1], bb[np*2+1][1],
                        sBu[bf] + SWZ128(n * 128 + col16 * 16));
            }
            #pragma unroll
            for (int mb = 0; mb < 2; mb++)
                #pragma unroll
                for (int nb = 0; nb < 4; nb++)
                    mma16816(acc[mb][nb], a[mb][0], a[mb][1], a[mb][2], a[mb][3],
                             bb[nb][0], bb[nb][1]);
        }
        __syncthreads();
    }

    #pragma unroll
    for (int mb = 0; mb < 2; mb++) {
        int mg = m0 + rt * 32 + mb * 16 + (lane >> 2);
        float* orow = out + (size_t)mg * NC + e0;
        #pragma unroll
        for (int nb = 0; nb < 4; nb++) {
            int n = ct * 32 + nb * 8 + (lane & 3) * 2;
            float2 bb2 = *(const float2*)(bp + e0 + n);
            *(float2*)(orow + n) =
                make_float2(acc[mb][nb][0] + bb2.x, acc[mb][nb][1] + bb2.y);
            *(float2*)(orow + 8*NC + n) =
                make_float2(acc[mb][nb][2] + bb2.x, acc[mb][nb][3] + bb2.y);
        }
    }
}

// ---------------------------------------------------------------------------

extern "C" void kernel_launch(void* const* d_in, const int* in_sizes, int n_in,
                              void* d_out, int out_size)
{
    const float* x  = (const float*)d_in[0];
    const float* Wq = (const float*)d_in[1];
    const float* Wk = (const float*)d_in[2];
    const float* Wv = (const float*)d_in[3];
    const float* Wp = (const float*)d_in[4];
    const float* bp = (const float*)d_in[5];
    float* out = (float*)d_out;

    convert_x_kernel<<<3072, 256>>>(x);
    convert_w_kernel<<<24, 256>>>(Wq, Wk, Wv, Wp);
    qkv_tc_kernel<<<dim3(NM/128, 18), 256>>>();
    attn_tc_kernel<<<dim3(NT/64, NB*NH), 128>>>();
    proj_tc_kernel<<<dim3(NM/128, NC/64), 256>>>(bp, out);
}

// round 9
// speedup vs baseline: 5.1858x; 1.3062x over previous
#include <cuda_runtime.h>
#include <cuda_fp16.h>
#include <cstdint>

#define NC 384
#define NH 6
#define HD 64
#define NB 64
#define NT 256
#define NM (NB*NT)
#define SOFT_SCALE 0.125f

// fp16 scratch (allocation-free rule: __device__ globals)
__device__ __align__(128) __half g_x16[(size_t)NM*NC];
__device__ __align__(128) __half g_wqkv16[(size_t)NH*3*HD*NC];  // [h][mat][n=64][k=384]
__device__ __align__(128) __half g_wp16[(size_t)NC*NC];         // [n=384][k=384]
__device__ __align__(128) __half g_q16[(size_t)NB*NH*NT*HD];    // pre-scaled by 1/8
__device__ __align__(128) __half g_k16[(size_t)NB*NH*NT*HD];
__device__ __align__(128) __half g_v16[(size_t)NB*NH*NT*HD];
__device__ __align__(128) __half g_att16[(size_t)NB*NH*NT*HD];

#define SWZ128(b) ((b) ^ (((b) >> 3) & 0x70))

static __device__ __forceinline__ uint32_t smem_u32(const void* p) {
    uint32_t a;
    asm("{ .reg .u64 t; cvta.to.shared.u64 t, %1; cvt.u32.u64 %0, t; }"
        : "=r"(a) : "l"(p));
    return a;
}
static __device__ __forceinline__ void ldsm_x4(
    uint32_t& r0, uint32_t& r1, uint32_t& r2, uint32_t& r3, uint32_t addr)
{
    asm volatile("ldmatrix.sync.aligned.m8n8.x4.shared.b16 {%0,%1,%2,%3}, [%4];"
                 : "=r"(r0), "=r"(r1), "=r"(r2), "=r"(r3) : "r"(addr));
}
static __device__ __forceinline__ void ldsm_x4_t(
    uint32_t& r0, uint32_t& r1, uint32_t& r2, uint32_t& r3, uint32_t addr)
{
    asm volatile("ldmatrix.sync.aligned.m8n8.x4.trans.shared.b16 {%0,%1,%2,%3}, [%4];"
                 : "=r"(r0), "=r"(r1), "=r"(r2), "=r"(r3) : "r"(addr));
}
static __device__ __forceinline__ void mma16816(
    float* c, uint32_t a0, uint32_t a1, uint32_t a2, uint32_t a3,
    uint32_t b0, uint32_t b1)
{
    asm volatile(
        "mma.sync.aligned.m16n8k16.row.col.f32.f16.f16.f32 "
        "{%0,%1,%2,%3}, {%4,%5,%6,%7}, {%8,%9}, {%0,%1,%2,%3};"
        : "+f"(c[0]), "+f"(c[1]), "+f"(c[2]), "+f"(c[3])
        : "r"(a0), "r"(a1), "r"(a2), "r"(a3), "r"(b0), "r"(b1));
}
static __device__ __forceinline__ uint32_t f2h2(float a, float b) {
    __half2 h = __floats2half2_rn(a, b);
    return *reinterpret_cast<uint32_t*>(&h);
}
#define CP_ASYNC16(d, s) \
    asm volatile("cp.async.ca.shared.global [%0], [%1], 16;" :: "r"(d), "l"(s))
#define CP_COMMIT() asm volatile("cp.async.commit_group;" ::: "memory")
#define CP_WAIT0()  asm volatile("cp.async.wait_group 0;" ::: "memory")
#define CP_WAIT1()  asm volatile("cp.async.wait_group 1;" ::: "memory")

// ===========================================================================
// Prologue: converts. blocks [0,3072): x -> fp16 (8 elems/thread).
// blocks [3072,3096): weights -> fp16 transposed to [n][k].
//   blk' < 18: qkv, mat=blk'/6, h=blk'%6, stored [h][mat][64][384]
//   blk' >= 18: Wp n-tile of 64.
// ===========================================================================
__global__ __launch_bounds__(256) void convert_all_kernel(
    const float* __restrict__ x,
    const float* __restrict__ Wq, const float* __restrict__ Wk,
    const float* __restrict__ Wv, const float* __restrict__ Wp)
{
    __shared__ __half tw[64 * 384];
    int tid = threadIdx.x;

    if (blockIdx.x < 3072) {
        size_t i = ((size_t)blockIdx.x * 256 + tid) * 8;
        float4 u = *(const float4*)(x + i);
        float4 v = *(const float4*)(x + i + 4);
        *(uint4*)(g_x16 + i) = make_uint4(f2h2(u.x,u.y), f2h2(u.z,u.w),
                                          f2h2(v.x,v.y), f2h2(v.z,v.w));
        return;
    }
    int blk = blockIdx.x - 3072;
    if (blk < 18) {
        const float* Wsrcs[3] = {Wq, Wk, Wv};
        int mat = blk / 6, h = blk % 6;
        const float* W = Wsrcs[mat] + (size_t)h * NC * HD;
        for (int e = tid; e < 384 * 16; e += 256) {
            int k = e >> 4, n4 = e & 15;
            float4 w = *(const float4*)(W + (size_t)k * HD + n4 * 4);
            tw[(n4*4+0) * 384 + k] = __float2half_rn(w.x);
            tw[(n4*4+1) * 384 + k] = __float2half_rn(w.y);
            tw[(n4*4+2) * 384 + k] = __float2half_rn(w.z);
            tw[(n4*4+3) * 384 + k] = __float2half_rn(w.w);
        }
        __syncthreads();
        uint4* dst = (uint4*)(g_wqkv16 + (size_t)(h * 3 + mat) * 64 * 384);
        for (int e = tid; e < 64 * 48; e += 256)
            dst[e] = *(uint4*)(tw + e * 8);
    } else {
        int n0 = (blk - 18) * 64;
        for (int e = tid; e < 384 * 16; e += 256) {
            int k = e >> 4, n4 = e & 15;
            float4 w = *(const float4*)(Wp + (size_t)k * NC + n0 + n4 * 4);
            tw[(n4*4+0) * 384 + k] = __float2half_rn(w.x);
            tw[(n4*4+1) * 384 + k] = __float2half_rn(w.y);
            tw[(n4*4+2) * 384 + k] = __float2half_rn(w.z);
            tw[(n4*4+3) * 384 + k] = __float2half_rn(w.w);
        }
        __syncthreads();
        uint4* dst = (uint4*)(g_wp16 + (size_t)n0 * 384);
        for (int e = tid; e < 64 * 48; e += 256)
            dst[e] = *(uint4*)(tw + e * 8);
    }
}

// ===========================================================================
// Kernel 1: QKV GEMM, 3 mats fused per head (n=192). grid (128, 6),
// block 384 (12 warps): rt=wid&3 (m 32-row tile), ct=wid>>2 (mat 0..2).
// Single-buffered smem (A 16KB + B 24KB = 40KB), K = 6 chunks of 64.
// Q outputs pre-scaled by SOFT_SCALE.
// ===========================================================================
__global__ __launch_bounds__(384) void qkv_tc_kernel()
{
    __shared__ __align__(1024) __half smA[128*64];
    __shared__ __align__(1024) __half smB[192*64];

    int tid = threadIdx.x;
    int wid = tid >> 5, lane = tid & 31;
    int rt = wid & 3, ct = wid >> 2;     // ct == mat
    int h  = blockIdx.y;
    int m0 = blockIdx.x * 128;

    const uint32_t sAu = smem_u32(smA);
    const uint32_t sBu = smem_u32(smB);
    const __half* wsrc = g_wqkv16 + (size_t)h * 192 * 384;

    float acc[2][8][4] = {};

    for (int c = 0; c < 6; c++) {
        int c0 = c * 64;
        // stage A (1024 ops) + B (1536 ops)
        for (int e = tid; e < 1024; e += 384) {
            int r = e >> 3, g = e & 7;
            CP_ASYNC16(sAu + SWZ128(r * 128 + g * 16),
                       g_x16 + (size_t)(m0 + r) * NC + c0 + g * 8);
        }
        for (int e = tid; e < 1536; e += 384) {
            int n = e >> 3, g = e & 7;
            CP_ASYNC16(sBu + SWZ128(n * 128 + g * 16),
                       wsrc + (size_t)n * 384 + c0 + g * 8);
        }
        CP_COMMIT(); CP_WAIT0();
        __syncthreads();

        #pragma unroll
        for (int ks = 0; ks < 4; ks++) {
            int col16 = ks * 2 + (lane >> 4);
            uint32_t a[2][4];
            #pragma unroll
            for (int mb = 0; mb < 2; mb++) {
                int row = rt * 32 + mb * 16 + (lane & 15);
                ldsm_x4(a[mb][0], a[mb][1], a[mb][2], a[mb][3],
                        sAu + SWZ128(row * 128 + col16 * 16));
            }
            uint32_t b[8][2];
            #pragma unroll
            for (int np = 0; np < 4; np++) {
                int n = ct * 64 + np * 16 + (lane & 15);
                ldsm_x4(b[np*2][0], b[np*2+1][0], b[np*2][1], b[np*2+1][1],
                        sBu + SWZ128(n * 128 + col16 * 16));
            }
            #pragma unroll
            for (int mb = 0; mb < 2; mb++)
                #pragma unroll
                for (int nb = 0; nb < 8; nb++)
                    mma16816(acc[mb][nb], a[mb][0], a[mb][1], a[mb][2], a[mb][3],
                             b[nb][0], b[nb][1]);
        }
        __syncthreads();
    }

    __half* const outs3[3] = {g_q16, g_k16, g_v16};
    __half* outp = outs3[ct];
    float sc = (ct == 0) ? SOFT_SCALE : 1.0f;
    #pragma unroll
    for (int mb = 0; mb < 2; mb++) {
        int mg = m0 + rt * 32 + mb * 16 + (lane >> 2);
        int b = mg >> 8, t = mg & 255;
        __half* orow = outp + ((size_t)(b * NH + h) * NT + t) * HD;
        #pragma unroll
        for (int nb = 0; nb < 8; nb++) {
            int n = nb * 8 + (lane & 3) * 2;
            *(uint32_t*)(orow + n)        = f2h2(acc[mb][nb][0]*sc, acc[mb][nb][1]*sc);
            *(uint32_t*)(orow + 8*HD + n) = f2h2(acc[mb][nb][2]*sc, acc[mb][nb][3]*sc);
        }
    }
}

// ===========================================================================
// Kernel 2: causal flash attention. grid (2, NB*NH), block 256 (8 warps).
// CTA = 128 q-rows (qt2), warp = 16 q-rows, Q frags in registers.
// K/V double-buffered; causal-inactive warps skip compute.
// Q is pre-scaled, so no per-element scaling here.
// ===========================================================================
__global__ __launch_bounds__(256) void attn_tc_kernel()
{
    __shared__ __align__(1024) __half smK[2][64*64];
    __shared__ __align__(1024) __half smV[2][64*64];

    int tid = threadIdx.x;
    int wid = tid >> 5, lane = tid & 31;
    int qt2 = blockIdx.x;
    int bh = blockIdx.y;

    const uint32_t sKu[2] = {smem_u32(smK[0]), smem_u32(smK[1])};
    const uint32_t sVu[2] = {smem_u32(smV[0]), smem_u32(smV[1])};
    const __half* qbase = g_q16 + (size_t)bh * NT * HD;
    const __half* kbase = g_k16 + (size_t)bh * NT * HD;
    const __half* vbase = g_v16 + (size_t)bh * NT * HD;

    // ---- stage this CTA's 128 Q rows into smK[0..1], load frags to regs ----
    #pragma unroll
    for (int i = 0; i < 4; i++) {
        int e = tid + i * 256;
        int r = e >> 3, g = e & 7;
        uint32_t dst = (r < 64) ? sKu[0] + SWZ128(r * 128 + g * 16)
                                : sKu[1] + SWZ128((r - 64) * 128 + g * 16);
        CP_ASYNC16(dst, qbase + (size_t)(qt2*128 + r) * HD + g * 8);
    }
    CP_COMMIT(); CP_WAIT0();
    __syncthreads();

    uint32_t qf[4][4];
    {
        int qrow = wid * 16 + (lane & 15);
        uint32_t qsrc = (qrow < 64) ? sKu[0] : sKu[1];
        int qr = qrow & 63;
        #pragma unroll
        for (int ks = 0; ks < 4; ks++) {
            int col16 = ks * 2 + (lane >> 4);
            ldsm_x4(qf[ks][0], qf[ks][1], qf[ks][2], qf[ks][3],
                    qsrc + SWZ128(qr * 128 + col16 * 16));
        }
    }
    __syncthreads();   // Q reads done; smK reusable

    auto issueKV = [&](int st) {
        int bf = st & 1;
        #pragma unroll
        for (int i = 0; i < 2; i++) {
            int e = tid + i * 256;
            int r = e >> 3, g = e & 7;
            CP_ASYNC16(sKu[bf] + SWZ128(r * 128 + g * 16),
                       kbase + (size_t)(st*64 + r) * HD + g * 8);
            CP_ASYNC16(sVu[bf] + SWZ128(r * 128 + g * 16),
                       vbase + (size_t)(st*64 + r) * HD + g * 8);
        }
    };
    issueKV(0); CP_COMMIT();

    float o[8][4] = {};
    float mrow[2] = {-1e30f, -1e30f};
    float lrow[2] = {};
    int lastTile = qt2 * 2 + (wid >> 2);   // last tile this warp computes
    int ntiles = qt2 * 2 + 2;

    for (int st = 0; st < ntiles; st++) {
        if (st < ntiles - 1) { issueKV(st + 1); CP_COMMIT(); CP_WAIT1(); }
        else                 { CP_WAIT0(); }
        __syncthreads();
        int bf = st & 1;

        if (st <= lastTile) {
            // ---- S = Q K^T ----
            float sacc[8][4] = {};
            #pragma unroll
            for (int ks = 0; ks < 4; ks++) {
                uint32_t b[8][2];
                int col16 = ks * 2 + (lane >> 4);
                #pragma unroll
                for (int np = 0; np < 4; np++) {
                    int n = np * 16 + (lane & 15);
                    ldsm_x4(b[np*2][0], b[np*2+1][0], b[np*2][1], b[np*2+1][1],
                            sKu[bf] + SWZ128(n * 128 + col16 * 16));
                }
                #pragma unroll
                for (int nb = 0; nb < 8; nb++)
                    mma16816(sacc[nb], qf[ks][0], qf[ks][1], qf[ks][2], qf[ks][3],
                             b[nb][0], b[nb][1]);
            }

            // ---- causal mask (diagonal tile only) ----
            if (st == lastTile) {
                int r0 = qt2*128 + wid*16 + (lane >> 2);
                #pragma unroll
                for (int nb = 0; nb < 8; nb++) {
                    int cg = st*64 + nb*8 + (lane & 3) * 2;
                    if (cg     > r0    ) sacc[nb][0] = -1e30f;
                    if (cg + 1 > r0    ) sacc[nb][1] = -1e30f;
                    if (cg     > r0 + 8) sacc[nb][2] = -1e30f;
                    if (cg + 1 > r0 + 8) sacc[nb][3] = -1e30f;
                }
            }

            // ---- online softmax (2 rows/thread, 4-lane reduce) ----
            #pragma unroll
            for (int hf = 0; hf < 2; hf++) {
                float mx = -1e30f;
                #pragma unroll
                for (int nb = 0; nb < 8; nb++)
                    mx = fmaxf(mx, fmaxf(sacc[nb][hf*2], sacc[nb][hf*2+1]));
                mx = fmaxf(mx, __shfl_xor_sync(0xffffffffu, mx, 1));
                mx = fmaxf(mx, __shfl_xor_sync(0xffffffffu, mx, 2));
                float mnew = fmaxf(mrow[hf], mx);
                float corr = __expf(mrow[hf] - mnew);
                float rs = 0.f;
                #pragma unroll
                for (int nb = 0; nb < 8; nb++) {
                    float p0 = __expf(sacc[nb][hf*2]   - mnew);
                    float p1 = __expf(sacc[nb][hf*2+1] - mnew);
                    sacc[nb][hf*2] = p0; sacc[nb][hf*2+1] = p1;
                    rs += p0 + p1;
                }
                rs += __shfl_xor_sync(0xffffffffu, rs, 1);
                rs += __shfl_xor_sync(0xffffffffu, rs, 2);
                lrow[hf] = lrow[hf] * corr + rs;
                mrow[hf] = mnew;
                #pragma unroll
                for (int nb = 0; nb < 8; nb++) {
                    o[nb][hf*2]   *= corr;
                    o[nb][hf*2+1] *= corr;
                }
            }

            // ---- O += P V (P in regs, V via ldmatrix.trans) ----
            #pragma unroll
            for (int ks = 0; ks < 4; ks++) {
                uint32_t pa0 = f2h2(sacc[ks*2  ][0], sacc[ks*2  ][1]);
                uint32_t pa1 = f2h2(sacc[ks*2  ][2], sacc[ks*2  ][3]);
                uint32_t pa2 = f2h2(sacc[ks*2+1][0], sacc[ks*2+1][1]);
                uint32_t pa3 = f2h2(sacc[ks*2+1][2], sacc[ks*2+1][3]);
                #pragma unroll
                for (int np = 0; np < 4; np++) {
                    int m = lane >> 3;
                    int row = ks * 16 + ((m & 1) << 3) + (lane & 7);
                    int colb = (np * 16 + ((m & 2) << 2)) * 2;
                    uint32_t v0, v1, v2, v3;
                    ldsm_x4_t(v0, v1, v2, v3, sVu[bf] + SWZ128(row * 128 + colb));
                    mma16816(o[np*2],   pa0, pa1, pa2, pa3, v0, v1);
                    mma16816(o[np*2+1], pa0, pa1, pa2, pa3, v2, v3);
                }
            }
        }
        __syncthreads();
    }

    // ---- epilogue ----
    float inv0 = 1.0f / lrow[0], inv1 = 1.0f / lrow[1];
    int t0 = qt2*128 + wid*16 + (lane >> 2);
    __half* ob = g_att16 + ((size_t)bh * NT + t0) * HD;
    #pragma unroll
    for (int nb = 0; nb < 8; nb++) {
        int n = nb*8 + (lane & 3) * 2;
        *(uint32_t*)(ob + n)        = f2h2(o[nb][0]*inv0, o[nb][1]*inv0);
        *(uint32_t*)(ob + 8*HD + n) = f2h2(o[nb][2]*inv1, o[nb][3]*inv1);
    }
}

// ===========================================================================
// Kernel 3: output projection + bias. grid (128, 6), block 256 (8 warps).
// Warp tile 32x32. K = 6 chunks of 64 (one head each), cp.async pipelined.
// ===========================================================================
__global__ __launch_bounds__(256) void proj_tc_kernel(
    const float* __restrict__ bp, float* __restrict__ out)
{
    __shared__ __align__(1024) __half smA[2][128*64];
    __shared__ __align__(1024) __half smB[2][64*64];

    int tid = threadIdx.x;
    int wid = tid >> 5, lane = tid & 31;
    int rt = wid & 3, ct = wid >> 2;
    int m0 = blockIdx.x * 128;
    int e0 = blockIdx.y * 64;
    int b  = m0 >> 8;
    int t0 = m0 & 255;

    const uint32_t sAu[2] = {smem_u32(smA[0]), smem_u32(smA[1])};
    const uint32_t sBu[2] = {smem_u32(smB[0]), smem_u32(smB[1])};

    float acc[2][4][4] = {};

    auto issue = [&](int hc) {
        int bf = hc & 1;
        const __half* abase = g_att16 + ((size_t)(b * NH + hc) * NT + t0) * HD;
        #pragma unroll
        for (int i = 0; i < 4; i++) {
            int e = tid + i * 256;
            int r = e >> 3, g = e & 7;
            CP_ASYNC16(sAu[bf] + SWZ128(r * 128 + g * 16),
                       abase + (size_t)r * HD + g * 8);
        }
        #pragma unroll
        for (int i = 0; i < 2; i++) {
            int e = tid + i * 256;
            int n = e >> 3, g = e & 7;
            CP_ASYNC16(sBu[bf] + SWZ128(n * 128 + g * 16),
                       g_wp16 + (size_t)(e0 + n) * 384 + hc * 64 + g * 8);
        }
    };

    issue(0); CP_COMMIT();
    for (int hc = 0; hc < 6; hc++) {
        if (hc < 5) { issue(hc + 1); CP_COMMIT(); CP_WAIT1(); }
        else        { CP_WAIT0(); }
        __syncthreads();
        int bf = hc & 1;
        #pragma unroll
        for (int ks = 0; ks < 4; ks++) {
            int col16 = ks * 2 + (lane >> 4);
            uint32_t a[2][4];
            #pragma unroll
            for (int mb = 0; mb < 2; mb++) {
                int row = rt * 32 + mb * 16 + (lane & 15);
                ldsm_x4(a[mb][0], a[mb][1], a[mb][2], a[mb][3],
                        sAu[bf] + SWZ128(row * 128 + col16 * 16));
            }
            uint32_t bb[4][2];
            #pragma unroll
            for (int np = 0; np < 2; np++) {
                int n = ct * 32 + np * 16 + (lane & 15);
                ldsm_x4(bb[np*2][0], bb[np*2+1][0], bb[np*2][1], bb[np*2+1][1],
                        sBu[bf] + SWZ128(n * 128 + col16 * 16));
            }
            #pragma unroll
            for (int mb = 0; mb < 2; mb++)
                #pragma unroll
                for (int nb = 0; nb < 4; nb++)
                    mma16816(acc[mb][nb], a[mb][0], a[mb][1], a[mb][2], a[mb][3],
                             bb[nb][0], bb[nb][1]);
        }
        __syncthreads();
    }

    #pragma unroll
    for (int mb = 0; mb < 2; mb++) {
        int mg = m0 + rt * 32 + mb * 16 + (lane >> 2);
        float* orow = out + (size_t)mg * NC + e0;
        #pragma unroll
        for (int nb = 0; nb < 4; nb++) {
            int n = ct * 32 + nb * 8 + (lane & 3) * 2;
            float2 bb2 = *(const float2*)(bp + e0 + n);
            *(float2*)(orow + n) =
                make_float2(acc[mb][nb][0] + bb2.x, acc[mb][nb][1] + bb2.y);
            *(float2*)(orow + 8*NC + n) =
                make_float2(acc[mb][nb][2] + bb2.x, acc[mb][nb][3] + bb2.y);
        }
    }
}

// ---------------------------------------------------------------------------

extern "C" void kernel_launch(void* const* d_in, const int* in_sizes, int n_in,
                              void* d_out, int out_size)
{
    const float* x  = (const float*)d_in[0];
    const float* Wq = (const float*)d_in[1];
    const float* Wk = (const float*)d_in[2];
    const float* Wv = (const float*)d_in[3];
    const float* Wp = (const float*)d_in[4];
    const float* bp = (const float*)d_in[5];
    float* out = (float*)d_out;

    convert_all_kernel<<<3096, 256>>>(x, Wq, Wk, Wv, Wp);
    qkv_tc_kernel<<<dim3(NM/128, NH), 384>>>();
    attn_tc_kernel<<<dim3(2, NB*NH), 256>>>();
    proj_tc_kernel<<<dim3(NM/128, NC/64), 256>>>(bp, out);
}